// round 13
// baseline (speedup 1.0000x reference)
#include <cuda_runtime.h>
#include <math.h>

#define IMG_W 512
#define IMG_H 512
#define NPLANE 48
#define PLANE (IMG_W * IMG_H)
#define TOT (NPLANE * PLANE)

#define T_V 32
#define EPSF 1e-8f

// ---------------------------------------------------------------------------
// Scratch (__device__ globals). RULE (R4-R9): never pass these symbols as
// host-side kernel arguments (host shadow symbol -> ATS writes -> +256MiB UVM
// backing -> harness guard). Device-code references only.
// g_v0 is overwritten in place with the reflectance by pass_hc.
// ---------------------------------------------------------------------------
__device__ float g_v0[TOT];            // vertical blur sigma=2 -> refl after hc
__device__ float g_v1[TOT];            // sigma=4
__device__ float g_v2[TOT];            // sigma=8
__device__ float2 g_part[NPLANE * IMG_H];
__device__ float2 g_stats[NPLANE];
__device__ unsigned g_cnt[NPLANE];     // zero-init; atomicInc wraps 511->0

// ---------------------------------------------------------------------------
// Compile-time Gaussian coefficients (literal args, non-template kernels only)
// ---------------------------------------------------------------------------
__host__ __device__ constexpr double cexp(double x) {
    double t = 1.0, s = 1.0;
    for (int k = 1; k < 60; k++) { t *= x / (double)k; s += t; }
    return s;
}

template <int R>
struct Gauss {
    float c[2 * R + 1];
    __host__ __device__ constexpr Gauss(double sigma, double wmul) : c{} {
        double S = 0.0;
        for (int i = -R; i <= R; i++)
            S += cexp(-(double)(i * i) / (2.0 * sigma * sigma));
        for (int i = -R; i <= R; i++)
            c[i + R] = (float)(wmul * cexp(-(double)(i * i) / (2.0 * sigma * sigma)) / S);
    }
};

// ---------------------------------------------------------------------------
// Pass VF: fused vertical blurs of log(rgb+eps), all three sigmas from one
// 49-deep register window (log computed inline; R3-proven idiom).
// Thread = one column, T_V output rows.
// ---------------------------------------------------------------------------
__global__ __launch_bounds__(256) void pass_vf(const float* __restrict__ rgb) {
    constexpr Gauss<6>  C0(2.0, 1.0);
    constexpr Gauss<12> C1(4.0, 1.0);
    constexpr Gauss<24> C2(8.0, 1.0);

    const int x = blockIdx.x * 256 + threadIdx.x;
    const int y0 = blockIdx.y * T_V;
    const int plane = blockIdx.z;
    const size_t po = (size_t)plane * PLANE;
    const float* src = rgb + po;

    float w[49];
#pragma unroll
    for (int j = 0; j < 48; j++) {
        int y = y0 - 24 + j;
        w[j] = (y >= 0 && y < IMG_H) ? logf(src[y * IMG_W + x] + EPSF) : 0.0f;
    }
#pragma unroll
    for (int t = 0; t < T_V; t++) {
        int y = y0 + t + 24;
        w[48] = (y < IMG_H) ? logf(src[y * IMG_W + x] + EPSF) : 0.0f;

        float s2 = 0.0f, s1 = 0.0f, s0 = 0.0f;
#pragma unroll
        for (int j = 0; j < 49; j++) s2 = fmaf(w[j], C2.c[j], s2);
#pragma unroll
        for (int j = 0; j < 25; j++) s1 = fmaf(w[12 + j], C1.c[j], s1);
#pragma unroll
        for (int j = 0; j < 13; j++) s0 = fmaf(w[18 + j], C0.c[j], s0);

        const size_t o = po + (size_t)(y0 + t) * IMG_W + x;
        g_v2[o] = s2;
        g_v1[o] = s1;
        g_v0[o] = s0;
#pragma unroll
        for (int j = 0; j < 48; j++) w[j] = w[j + 1];
    }
}

// ---------------------------------------------------------------------------
// Pass HC: horizontal blurs of the three v-fields (weights folded in),
// refl = log(rgb) - illum written in place over g_v0, per-row stats partial,
// and a last-block (per plane) fold of all 512 partials -> g_stats.
// One block per (plane, row); 128 threads x 4 px.
// ---------------------------------------------------------------------------
__global__ __launch_bounds__(128) void pass_hc(const float* __restrict__ rgb) {
    constexpr Gauss<6>  C0(2.0, 1.0 / 2.25);
    constexpr Gauss<12> C1(4.0, 0.75 / 2.25);
    constexpr Gauss<24> C2(8.0, 0.5 / 2.25);

    __shared__ __align__(16) float s0[560], s1[560], s2[560];
    __shared__ float ssum[4], ssq[4];
    __shared__ int slast;

    const int plane = blockIdx.y;
    const int y = blockIdx.x;
    const int tid = threadIdx.x;
    const size_t ro = (size_t)plane * PLANE + (size_t)y * IMG_W;
    const int x0 = tid * 4;

    for (int i = tid; i < 560; i += 128) {
        int x = i - 24;
        bool in = (x >= 0 && x < IMG_W);
        s0[i] = in ? g_v0[ro + x] : 0.0f;
        s1[i] = in ? g_v1[ro + x] : 0.0f;
        s2[i] = in ? g_v2[ro + x] : 0.0f;
    }
    __syncthreads();

    float il[4] = {0.0f, 0.0f, 0.0f, 0.0f};

    {   // sigma=8: window s2[x0 .. x0+51]
        float w[52];
        const float4* p4 = reinterpret_cast<const float4*>(s2 + x0);
#pragma unroll
        for (int j = 0; j < 13; j++) {
            float4 v = p4[j];
            w[4 * j] = v.x; w[4 * j + 1] = v.y; w[4 * j + 2] = v.z; w[4 * j + 3] = v.w;
        }
#pragma unroll
        for (int p = 0; p < 4; p++) {
            float a = 0.0f;
#pragma unroll
            for (int j = 0; j < 49; j++) a = fmaf(w[p + j], C2.c[j], a);
            il[p] += a;
        }
    }
    {   // sigma=4: window s1[x0+12 .. x0+39]
        float w[28];
        const float4* p4 = reinterpret_cast<const float4*>(s1 + x0 + 12);
#pragma unroll
        for (int j = 0; j < 7; j++) {
            float4 v = p4[j];
            w[4 * j] = v.x; w[4 * j + 1] = v.y; w[4 * j + 2] = v.z; w[4 * j + 3] = v.w;
        }
#pragma unroll
        for (int p = 0; p < 4; p++) {
            float a = 0.0f;
#pragma unroll
            for (int j = 0; j < 25; j++) a = fmaf(w[p + j], C1.c[j], a);
            il[p] += a;
        }
    }
    {   // sigma=2: window s0[x0+16 .. x0+35], taps at [2..17]
        float w[20];
        const float4* p4 = reinterpret_cast<const float4*>(s0 + x0 + 16);
#pragma unroll
        for (int j = 0; j < 5; j++) {
            float4 v = p4[j];
            w[4 * j] = v.x; w[4 * j + 1] = v.y; w[4 * j + 2] = v.z; w[4 * j + 3] = v.w;
        }
#pragma unroll
        for (int p = 0; p < 4; p++) {
            float a = 0.0f;
#pragma unroll
            for (int j = 0; j < 13; j++) a = fmaf(w[p + 2 + j], C0.c[j], a);
            il[p] += a;
        }
    }

    // reflectance (log recomputed from rgb) written in place over g_v0
    const float4 rgb4 = *reinterpret_cast<const float4*>(rgb + ro + x0);
    float r[4];
    r[0] = logf(rgb4.x + EPSF) - il[0];
    r[1] = logf(rgb4.y + EPSF) - il[1];
    r[2] = logf(rgb4.z + EPSF) - il[2];
    r[3] = logf(rgb4.w + EPSF) - il[3];

    *reinterpret_cast<float4*>(&g_v0[ro + x0]) = make_float4(r[0], r[1], r[2], r[3]);

    float psum = 0.0f, psq = 0.0f;
#pragma unroll
    for (int p = 0; p < 4; p++) { psum += r[p]; psq = fmaf(r[p], r[p], psq); }

#pragma unroll
    for (int off = 16; off; off >>= 1) {
        psum += __shfl_down_sync(0xffffffffu, psum, off);
        psq  += __shfl_down_sync(0xffffffffu, psq, off);
    }
    const int lane = tid & 31, wid = tid >> 5;
    if (lane == 0) { ssum[wid] = psum; ssq[wid] = psq; }
    __syncthreads();
    if (tid == 0) {
        float a = 0.0f, b = 0.0f;
#pragma unroll
        for (int i = 0; i < 4; i++) { a += ssum[i]; b += ssq[i]; }
        g_part[plane * IMG_H + y] = make_float2(a, b);
        __threadfence();
        unsigned old = atomicInc(&g_cnt[plane], IMG_H - 1);  // wraps 511 -> 0
        slast = (old == IMG_H - 1);
    }
    __syncthreads();

    // Last block of this plane folds all 512 partials (deterministic order).
    if (slast) {
        float s = 0.0f, q = 0.0f;
#pragma unroll
        for (int k = 0; k < 4; k++) {
            float2 p = g_part[plane * IMG_H + tid + k * 128];
            s += p.x; q += p.y;
        }
#pragma unroll
        for (int off = 16; off; off >>= 1) {
            s += __shfl_down_sync(0xffffffffu, s, off);
            q += __shfl_down_sync(0xffffffffu, q, off);
        }
        if (lane == 0) { ssum[wid] = s; ssq[wid] = q; }
        __syncthreads();
        if (tid == 0) {
            float S = 0.0f, Q = 0.0f;
#pragma unroll
            for (int i = 0; i < 4; i++) { S += ssum[i]; Q += ssq[i]; }
            const float N = (float)PLANE;
            float mean = S / N;
            float var = (Q - S * S / N) / (N - 1.0f);
            float stdv = sqrtf(var);
            g_stats[plane] = make_float2(mean, 1.0f / (stdv + EPSF));
        }
    }
}

// ---------------------------------------------------------------------------
// Pass F: normalize, exp, clip to [0,1].  (g_v0 holds refl.)
// ---------------------------------------------------------------------------
__global__ __launch_bounds__(256) void pass_f(float* __restrict__ out) {
    const unsigned i = (blockIdx.x * 256u + threadIdx.x) * 4u;
    const unsigned plane = i >> 18;
    const float2 st = g_stats[plane];
    const float mean = st.x, inv = st.y;

    float4 r = *reinterpret_cast<const float4*>(&g_v0[i]);
    float4 o;
    o.x = fminf(expf((r.x - mean) * inv), 1.0f);
    o.y = fminf(expf((r.y - mean) * inv), 1.0f);
    o.z = fminf(expf((r.z - mean) * inv), 1.0f);
    o.w = fminf(expf((r.w - mean) * inv), 1.0f);
    *reinterpret_cast<float4*>(&out[i]) = o;
}

// ---------------------------------------------------------------------------
// Launch — 3 kernels; no __device__ symbol in any argument list.
// ---------------------------------------------------------------------------
extern "C" void kernel_launch(void* const* d_in, const int* in_sizes, int n_in,
                              void* d_out, int out_size) {
    const float* rgb = (const float*)d_in[0];
    float* out = (float*)d_out;

    pass_vf<<<dim3(2, IMG_H / T_V, NPLANE), 256>>>(rgb);
    pass_hc<<<dim3(IMG_H, NPLANE), 128>>>(rgb);
    pass_f<<<TOT / 1024, 256>>>(out);
}

// round 14
// speedup vs baseline: 1.3849x; 1.3849x over previous
#include <cuda_runtime.h>
#include <math.h>

#define IMG_W 512
#define IMG_H 512
#define NPLANE 48
#define PLANE (IMG_W * IMG_H)
#define TOT (NPLANE * PLANE)

#define T_V 32
#define EPSF 1e-8f

// ---------------------------------------------------------------------------
// Scratch (__device__ globals). RULE (R4-R9): never pass these symbols as
// host-side kernel arguments. Device-code references only.
// g_log: log(rgb+eps) after pass_l; overwritten with reflectance by pass_hc.
// ---------------------------------------------------------------------------
__device__ float g_log[TOT];
__device__ float g_v0[TOT];            // vertical blur sigma=2
__device__ float g_v1[TOT];            // sigma=4
__device__ float g_v2[TOT];            // sigma=8
__device__ float2 g_part[NPLANE * IMG_H];
__device__ float2 g_stats[NPLANE];
__device__ unsigned g_cnt[NPLANE];     // zero-init; atomicInc wraps 511->0

// ---------------------------------------------------------------------------
// Compile-time Gaussian coefficients (literal args, non-template kernels only)
// ---------------------------------------------------------------------------
__host__ __device__ constexpr double cexp(double x) {
    double t = 1.0, s = 1.0;
    for (int k = 1; k < 60; k++) { t *= x / (double)k; s += t; }
    return s;
}

template <int R>
struct Gauss {
    float c[2 * R + 1];
    __host__ __device__ constexpr Gauss(double sigma, double wmul) : c{} {
        double S = 0.0;
        for (int i = -R; i <= R; i++)
            S += cexp(-(double)(i * i) / (2.0 * sigma * sigma));
        for (int i = -R; i <= R; i++)
            c[i + R] = (float)(wmul * cexp(-(double)(i * i) / (2.0 * sigma * sigma)) / S);
    }
};

// ---------------------------------------------------------------------------
// Pass L: elementwise log(rgb + eps) -> g_log
// ---------------------------------------------------------------------------
__global__ __launch_bounds__(256) void pass_l(const float* __restrict__ rgb) {
    const unsigned i = (blockIdx.x * 256u + threadIdx.x) * 4u;
    float4 v = *reinterpret_cast<const float4*>(rgb + i);
    float4 o;
    o.x = logf(v.x + EPSF);
    o.y = logf(v.y + EPSF);
    o.z = logf(v.z + EPSF);
    o.w = logf(v.w + EPSF);
    *reinterpret_cast<float4*>(&g_log[i]) = o;
}

// ---------------------------------------------------------------------------
// Pass VF: fused vertical blurs of g_log, all three sigmas from one 49-float
// CIRCULAR register window (indices compile-time constants under full unroll;
// no shift chain -> ~48 fewer MOVs per output row vs R11/R13).
// Window invariant: row r lives in w[(r - (y0-24)) % 49].
// ---------------------------------------------------------------------------
__global__ __launch_bounds__(256) void pass_vf() {
    constexpr Gauss<6>  C0(2.0, 1.0);
    constexpr Gauss<12> C1(4.0, 1.0);
    constexpr Gauss<24> C2(8.0, 1.0);

    const int x = blockIdx.x * 256 + threadIdx.x;
    const int y0 = blockIdx.y * T_V;
    const int plane = blockIdx.z;
    const size_t po = (size_t)plane * PLANE;
    const float* src = g_log + po;

    float w[49];
#pragma unroll
    for (int j = 0; j < 48; j++) {
        int y = y0 - 24 + j;
        w[j] = (y >= 0 && y < IMG_H) ? src[y * IMG_W + x] : 0.0f;
    }
#pragma unroll
    for (int t = 0; t < T_V; t++) {
        int y = y0 + t + 24;
        w[(48 + t) % 49] = (y < IMG_H) ? src[y * IMG_W + x] : 0.0f;

        float s2 = 0.0f, s1 = 0.0f, s0 = 0.0f;
#pragma unroll
        for (int j = 0; j < 49; j++) s2 = fmaf(w[(t + j) % 49], C2.c[j], s2);
#pragma unroll
        for (int j = 0; j < 25; j++) s1 = fmaf(w[(t + 12 + j) % 49], C1.c[j], s1);
#pragma unroll
        for (int j = 0; j < 13; j++) s0 = fmaf(w[(t + 18 + j) % 49], C0.c[j], s0);

        const size_t o = po + (size_t)(y0 + t) * IMG_W + x;
        g_v2[o] = s2;
        g_v1[o] = s1;
        g_v0[o] = s0;
    }
}

// ---------------------------------------------------------------------------
// Pass HC: horizontal blurs of the three v-fields (weights folded in),
// refl = g_log - illum written in place over g_log, per-row stats partial,
// last-block-per-plane fold -> g_stats. One block per (plane, row).
// ---------------------------------------------------------------------------
__global__ __launch_bounds__(128) void pass_hc() {
    constexpr Gauss<6>  C0(2.0, 1.0 / 2.25);
    constexpr Gauss<12> C1(4.0, 0.75 / 2.25);
    constexpr Gauss<24> C2(8.0, 0.5 / 2.25);

    __shared__ __align__(16) float s0[560], s1[560], s2[560];
    __shared__ float ssum[4], ssq[4];
    __shared__ int slast;

    const int plane = blockIdx.y;
    const int y = blockIdx.x;
    const int tid = threadIdx.x;
    const size_t ro = (size_t)plane * PLANE + (size_t)y * IMG_W;
    const int x0 = tid * 4;

    for (int i = tid; i < 560; i += 128) {
        int x = i - 24;
        bool in = (x >= 0 && x < IMG_W);
        s0[i] = in ? g_v0[ro + x] : 0.0f;
        s1[i] = in ? g_v1[ro + x] : 0.0f;
        s2[i] = in ? g_v2[ro + x] : 0.0f;
    }
    __syncthreads();

    float il[4] = {0.0f, 0.0f, 0.0f, 0.0f};

    {   // sigma=8: window s2[x0 .. x0+51]
        float w[52];
        const float4* p4 = reinterpret_cast<const float4*>(s2 + x0);
#pragma unroll
        for (int j = 0; j < 13; j++) {
            float4 v = p4[j];
            w[4 * j] = v.x; w[4 * j + 1] = v.y; w[4 * j + 2] = v.z; w[4 * j + 3] = v.w;
        }
#pragma unroll
        for (int p = 0; p < 4; p++) {
            float a = 0.0f;
#pragma unroll
            for (int j = 0; j < 49; j++) a = fmaf(w[p + j], C2.c[j], a);
            il[p] += a;
        }
    }
    {   // sigma=4: window s1[x0+12 .. x0+39]
        float w[28];
        const float4* p4 = reinterpret_cast<const float4*>(s1 + x0 + 12);
#pragma unroll
        for (int j = 0; j < 7; j++) {
            float4 v = p4[j];
            w[4 * j] = v.x; w[4 * j + 1] = v.y; w[4 * j + 2] = v.z; w[4 * j + 3] = v.w;
        }
#pragma unroll
        for (int p = 0; p < 4; p++) {
            float a = 0.0f;
#pragma unroll
            for (int j = 0; j < 25; j++) a = fmaf(w[p + j], C1.c[j], a);
            il[p] += a;
        }
    }
    {   // sigma=2: window s0[x0+16 .. x0+35], taps at [2..17]
        float w[20];
        const float4* p4 = reinterpret_cast<const float4*>(s0 + x0 + 16);
#pragma unroll
        for (int j = 0; j < 5; j++) {
            float4 v = p4[j];
            w[4 * j] = v.x; w[4 * j + 1] = v.y; w[4 * j + 2] = v.z; w[4 * j + 3] = v.w;
        }
#pragma unroll
        for (int p = 0; p < 4; p++) {
            float a = 0.0f;
#pragma unroll
            for (int j = 0; j < 13; j++) a = fmaf(w[p + 2 + j], C0.c[j], a);
            il[p] += a;
        }
    }

    // reflectance in place over g_log + stats partial
    const float4 lg4 = *reinterpret_cast<const float4*>(g_log + ro + x0);
    float r[4];
    r[0] = lg4.x - il[0];
    r[1] = lg4.y - il[1];
    r[2] = lg4.z - il[2];
    r[3] = lg4.w - il[3];

    *reinterpret_cast<float4*>(&g_log[ro + x0]) = make_float4(r[0], r[1], r[2], r[3]);

    float psum = 0.0f, psq = 0.0f;
#pragma unroll
    for (int p = 0; p < 4; p++) { psum += r[p]; psq = fmaf(r[p], r[p], psq); }

#pragma unroll
    for (int off = 16; off; off >>= 1) {
        psum += __shfl_down_sync(0xffffffffu, psum, off);
        psq  += __shfl_down_sync(0xffffffffu, psq, off);
    }
    const int lane = tid & 31, wid = tid >> 5;
    if (lane == 0) { ssum[wid] = psum; ssq[wid] = psq; }
    __syncthreads();
    if (tid == 0) {
        float a = 0.0f, b = 0.0f;
#pragma unroll
        for (int i = 0; i < 4; i++) { a += ssum[i]; b += ssq[i]; }
        g_part[plane * IMG_H + y] = make_float2(a, b);
        __threadfence();
        unsigned old = atomicInc(&g_cnt[plane], IMG_H - 1);  // wraps 511 -> 0
        slast = (old == IMG_H - 1);
    }
    __syncthreads();

    // Last block of this plane folds all 512 partials (deterministic order).
    if (slast) {
        float s = 0.0f, q = 0.0f;
#pragma unroll
        for (int k = 0; k < 4; k++) {
            float2 p = g_part[plane * IMG_H + tid + k * 128];
            s += p.x; q += p.y;
        }
#pragma unroll
        for (int off = 16; off; off >>= 1) {
            s += __shfl_down_sync(0xffffffffu, s, off);
            q += __shfl_down_sync(0xffffffffu, q, off);
        }
        if (lane == 0) { ssum[wid] = s; ssq[wid] = q; }
        __syncthreads();
        if (tid == 0) {
            float S = 0.0f, Q = 0.0f;
#pragma unroll
            for (int i = 0; i < 4; i++) { S += ssum[i]; Q += ssq[i]; }
            const float N = (float)PLANE;
            float mean = S / N;
            float var = (Q - S * S / N) / (N - 1.0f);
            float stdv = sqrtf(var);
            g_stats[plane] = make_float2(mean, 1.0f / (stdv + EPSF));
        }
    }
}

// ---------------------------------------------------------------------------
// Pass F: normalize, exp, clip to [0,1].  (g_log holds refl.)
// ---------------------------------------------------------------------------
__global__ __launch_bounds__(256) void pass_f(float* __restrict__ out) {
    const unsigned i = (blockIdx.x * 256u + threadIdx.x) * 4u;
    const unsigned plane = i >> 18;
    const float2 st = g_stats[plane];
    const float mean = st.x, inv = st.y;

    float4 r = *reinterpret_cast<const float4*>(&g_log[i]);
    float4 o;
    o.x = fminf(expf((r.x - mean) * inv), 1.0f);
    o.y = fminf(expf((r.y - mean) * inv), 1.0f);
    o.z = fminf(expf((r.z - mean) * inv), 1.0f);
    o.w = fminf(expf((r.w - mean) * inv), 1.0f);
    *reinterpret_cast<float4*>(&out[i]) = o;
}

// ---------------------------------------------------------------------------
// Launch — 4 kernels; no __device__ symbol in any argument list.
// ---------------------------------------------------------------------------
extern "C" void kernel_launch(void* const* d_in, const int* in_sizes, int n_in,
                              void* d_out, int out_size) {
    const float* rgb = (const float*)d_in[0];
    float* out = (float*)d_out;

    pass_l<<<TOT / 1024, 256>>>(rgb);
    pass_vf<<<dim3(2, IMG_H / T_V, NPLANE), 256>>>();
    pass_hc<<<dim3(IMG_H, NPLANE), 128>>>();
    pass_f<<<TOT / 1024, 256>>>(out);
}